// round 1
// baseline (speedup 1.0000x reference)
#include <cuda_runtime.h>
#include <math.h>

// Problem constants
#define BATCH 512
#define SEQ   80
#define NV    36
#define NC    16
#define ANGLE 128
#define EMB   64
#define HID   512
#define FEAT  2176
#define INDIM 2240   // EMB + FEAT
#define GATES 2048   // 4*HID

// ---------------- scratch (single __device__ buffer, offsets in floats) ----
#define O_TDENSE 0u
#define O_TFEAT  1114112u            // 512*2176
#define O_XV     2228224u
#define O_XO     3375104u            // + 512*2240
#define O_GV     4521984u
#define O_GO     5570560u            // + 512*2048
#define O_HCV    6619136u
#define O_HCO    7143424u            // + 512*1024
#define O_TAVV   7667712u
#define O_TAVO   7929856u            // + 512*512
#define O_HC2    8192000u
#define O_TCAND  8716288u
#define SCRATCH_FLOATS 9830400u

__device__ float g_scratch[SCRATCH_FLOATS];

// output offsets (floats) in d_out
#define OFF_H1V   0u
#define OFF_H1O   262144u
#define OFF_C1V   524288u
#define OFF_C1O   786432u
#define OFF_LOGIT 1048576u
#define OFF_HTV   1056768u
#define OFF_HTO   1318912u

// ---------------- generic NT SGEMM: C = A[M,K] * B[N,K]^T ------------------
// 64x64 tile, BK=16, 256 threads, 4x4 per-thread microtile, float4 paths.
// Optional: accumulate into C, add bias[n], tanh epilogue, dual write C2.
#define BM 64
#define BN 64
#define BK 16

__global__ __launch_bounds__(256) void gemm_nt_kernel(
    const float* __restrict__ A, const float* __restrict__ Bw,
    float* __restrict__ C, float* __restrict__ C2,
    const float* __restrict__ bias,
    int M, int N, int K, int lda, int ldb, int ldc, int ldc2,
    int accumulate, int do_tanh)
{
    __shared__ float As[BK][BM];
    __shared__ float Bs[BK][BN];
    const int tid = threadIdx.x;
    const int m0 = blockIdx.y * BM;
    const int n0 = blockIdx.x * BN;
    const int lr = tid >> 2;          // 0..63 (row within tile)
    const int lc = (tid & 3) * 4;     // 0,4,8,12 (col within BK)
    const int ty = tid >> 4;          // 0..15
    const int tx = tid & 15;          // 0..15

    float acc[4][4];
#pragma unroll
    for (int i = 0; i < 4; i++)
#pragma unroll
        for (int j = 0; j < 4; j++) acc[i][j] = 0.f;

    const float* Aptr = A + (size_t)(m0 + lr) * lda + lc;
    const float* Bptr = Bw + (size_t)(n0 + lr) * ldb + lc;

    for (int k0 = 0; k0 < K; k0 += BK) {
        float4 av = *reinterpret_cast<const float4*>(Aptr + k0);
        float4 bv = *reinterpret_cast<const float4*>(Bptr + k0);
        __syncthreads();
        As[lc + 0][lr] = av.x; As[lc + 1][lr] = av.y;
        As[lc + 2][lr] = av.z; As[lc + 3][lr] = av.w;
        Bs[lc + 0][lr] = bv.x; Bs[lc + 1][lr] = bv.y;
        Bs[lc + 2][lr] = bv.z; Bs[lc + 3][lr] = bv.w;
        __syncthreads();
#pragma unroll
        for (int kk = 0; kk < BK; kk++) {
            float4 a4 = *reinterpret_cast<const float4*>(&As[kk][ty * 4]);
            float4 b4 = *reinterpret_cast<const float4*>(&Bs[kk][tx * 4]);
            float a[4] = {a4.x, a4.y, a4.z, a4.w};
            float b[4] = {b4.x, b4.y, b4.z, b4.w};
#pragma unroll
            for (int i = 0; i < 4; i++)
#pragma unroll
                for (int j = 0; j < 4; j++) acc[i][j] = fmaf(a[i], b[j], acc[i][j]);
        }
    }

#pragma unroll
    for (int i = 0; i < 4; i++) {
        const int m = m0 + ty * 4 + i;
#pragma unroll
        for (int j = 0; j < 4; j++) {
            const int n = n0 + tx * 4 + j;
            float v = acc[i][j];
            if (accumulate) v += C[(size_t)m * ldc + n];
            if (bias) v += bias[n];
            if (do_tanh) v = tanhf(v);
            C[(size_t)m * ldc + n] = v;
            if (C2) C2[(size_t)m * ldc2 + n] = v;
        }
    }
}

// ---------------- fused object/feature attention (online softmax) ----------
// One block per batch row b. out[b, :] = softmax(feat[b] @ target[b]) @ feat[b]
__global__ __launch_bounds__(256) void attn_obj_kernel(
    const float* __restrict__ feat, const float* __restrict__ target,
    const int* __restrict__ mask, float* __restrict__ outp, int out_ld)
{
    __shared__ float tgt[FEAT];
    __shared__ float acc[FEAT];
    __shared__ float row[FEAT];
    __shared__ float red[8];
    __shared__ float s_w, s_sc, s_d;
    const int b = blockIdx.x, tid = threadIdx.x;

    for (int j = tid; j < FEAT; j += 256) {
        tgt[j] = target[(size_t)b * FEAT + j];
        acc[j] = 0.f;
    }
    float m_run = -3.0e38f, d_run = 0.f;
    __syncthreads();

    for (int s = 0; s < NV; s++) {
        const float* fr = feat + ((size_t)b * NV + s) * FEAT;
        float p = 0.f;
        for (int j = tid; j < FEAT; j += 256) {
            float x = fr[j];
            row[j] = x;
            p = fmaf(x, tgt[j], p);
        }
#pragma unroll
        for (int o = 16; o > 0; o >>= 1) p += __shfl_xor_sync(~0u, p, o);
        if ((tid & 31) == 0) red[tid >> 5] = p;
        __syncthreads();
        if (tid == 0) {
            float l = red[0] + red[1] + red[2] + red[3] + red[4] + red[5] + red[6] + red[7];
            if (mask && mask[b * NV + s]) l = -1e30f;
            float nm = fmaxf(m_run, l);
            float sc = expf(m_run - nm);
            float w  = expf(l - nm);
            m_run = nm;
            d_run = d_run * sc + w;
            s_w = w; s_sc = sc; s_d = d_run;
        }
        __syncthreads();
        const float w = s_w, sc = s_sc;
        for (int j = tid; j < FEAT; j += 256) acc[j] = fmaf(w, row[j], acc[j] * sc);
        __syncthreads();
    }
    const float dinv = 1.f / s_d;
    for (int j = tid; j < FEAT; j += 256)
        outp[(size_t)b * out_ld + j] = acc[j] * dinv;
}

// ---------------- fused masked context attention (two-pass, 80 logits) -----
__global__ __launch_bounds__(256) void attn_ctx_kernel(
    const float* __restrict__ ctx, const float* __restrict__ target,
    const int* __restrict__ mask, float* __restrict__ outp, int out_ld)
{
    __shared__ float tgt[HID];
    __shared__ float lg[SEQ];
    __shared__ float p[SEQ];
    __shared__ float s_d;
    const int b = blockIdx.x, tid = threadIdx.x;
    const int lane = tid & 31, w = tid >> 5;

    for (int j = tid; j < HID; j += 256) tgt[j] = target[(size_t)b * HID + j];
    __syncthreads();

    for (int s = w; s < SEQ; s += 8) {
        const float* cr = ctx + ((size_t)b * SEQ + s) * HID;
        float acc = 0.f;
        for (int j = lane; j < HID; j += 32) acc = fmaf(cr[j], tgt[j], acc);
#pragma unroll
        for (int o = 16; o > 0; o >>= 1) acc += __shfl_xor_sync(~0u, acc, o);
        if (lane == 0) lg[s] = mask[b * SEQ + s] ? -1e30f : acc;
    }
    __syncthreads();
    if (tid == 0) {
        float m = -3.0e38f;
        for (int s = 0; s < SEQ; s++) m = fmaxf(m, lg[s]);
        float d = 0.f;
        for (int s = 0; s < SEQ; s++) { float e = expf(lg[s] - m); p[s] = e; d += e; }
        s_d = d;
    }
    __syncthreads();
    const float dinv = 1.f / s_d;
    for (int j = tid; j < HID; j += 256) {
        float sum = 0.f;
        for (int s = 0; s < SEQ; s++)
            sum = fmaf(p[s], ctx[((size_t)b * SEQ + s) * HID + j], sum);
        outp[(size_t)b * out_ld + j] = sum * dinv;
    }
}

// ---------------- LSTM cell elementwise --------------------------------
__global__ __launch_bounds__(256) void lstm_cell_kernel(
    const float* __restrict__ gates, const float* __restrict__ bih,
    const float* __restrict__ bhh, const float* __restrict__ c0,
    float* __restrict__ h_out, float* __restrict__ c_out,
    float* __restrict__ h_out2, int ld2)
{
    const int idx = blockIdx.x * 256 + threadIdx.x;   // < 512*512
    const int b = idx >> 9, j = idx & 511;
    const float* gr = gates + (size_t)b * GATES;
    float gi = gr[j]        + bih[j]        + bhh[j];
    float gf = gr[512 + j]  + bih[512 + j]  + bhh[512 + j];
    float gg = gr[1024 + j] + bih[1024 + j] + bhh[1024 + j];
    float go = gr[1536 + j] + bih[1536 + j] + bhh[1536 + j];
    float si = 1.f / (1.f + expf(-gi));
    float sf = 1.f / (1.f + expf(-gf));
    float so = 1.f / (1.f + expf(-go));
    float c1 = sf * c0[idx] + si * tanhf(gg);
    float h1 = so * tanhf(c1);
    h_out[idx] = h1;
    c_out[idx] = c1;
    h_out2[(size_t)b * ld2 + j] = h1;
}

// ---------------- candidate logits: warp per (b,c) dot over FEAT -----------
__global__ __launch_bounds__(256) void cand_logits_kernel(
    const float* __restrict__ cand, const float* __restrict__ T,
    float* __restrict__ out)
{
    const int wid = (blockIdx.x * 256 + threadIdx.x) >> 5;   // 0..8191
    const int lane = threadIdx.x & 31;
    const int b = wid >> 4, c = wid & 15;
    const float* cr = cand + ((size_t)b * NC + c) * FEAT;
    const float* tr = T + (size_t)b * FEAT;
    float acc = 0.f;
    for (int j = lane; j < FEAT; j += 32) acc = fmaf(cr[j], tr[j], acc);
#pragma unroll
    for (int o = 16; o > 0; o >>= 1) acc += __shfl_xor_sync(~0u, acc, o);
    if (lane == 0) out[wid] = acc;
}

// ---------------- launch ---------------------------------------------------
static inline void gemm(const float* A, const float* B, float* C, int M, int N,
                        int K, int lda, int ldb, int ldc,
                        float* C2 = nullptr, int ldc2 = 0,
                        const float* bias = nullptr, int accumulate = 0,
                        int do_tanh = 0)
{
    dim3 grid(N / BN, M / BM);
    gemm_nt_kernel<<<grid, 256>>>(A, B, C, C2, bias, M, N, K, lda, ldb, ldc,
                                  ldc2, accumulate, do_tanh);
}

extern "C" void kernel_launch(void* const* d_in, const int* in_sizes, int n_in,
                              void* d_out, int out_size)
{
    const float* action    = (const float*)d_in[0];
    const float* cand_feat = (const float*)d_in[1];
    const float* prev_h1_v = (const float*)d_in[2];
    const float* prev_h1_o = (const float*)d_in[3];
    // d_in[4] = c_0_v (unused by reference)
    const float* c_0_o     = (const float*)d_in[5];
    const float* ctx       = (const float*)d_in[6];
    const int*   ctx_mask  = (const int*)d_in[7];
    const float* feature   = (const float*)d_in[8];
    const float* denseObj  = (const float*)d_in[9];
    const int*   obj_mask  = (const int*)d_in[10];
    const float* W_emb     = (const float*)d_in[11];
    const float* b_emb     = (const float*)d_in[12];
    const float* Wih_v     = (const float*)d_in[13];
    const float* Whh_v     = (const float*)d_in[14];
    const float* bih_v     = (const float*)d_in[15];
    const float* bhh_v     = (const float*)d_in[16];
    const float* Wih_o     = (const float*)d_in[17];
    const float* Whh_o     = (const float*)d_in[18];
    const float* bih_o     = (const float*)d_in[19];
    const float* bhh_o     = (const float*)d_in[20];
    const float* Wq_feat   = (const float*)d_in[21];
    const float* Wq_dense  = (const float*)d_in[22];
    const float* Wq_av     = (const float*)d_in[23];
    const float* Wo_av     = (const float*)d_in[24];
    const float* Wq_ao     = (const float*)d_in[25];
    const float* Wo_ao     = (const float*)d_in[26];
    const float* Wq_cand   = (const float*)d_in[27];
    float* out = (float*)d_out;

    float* scr = nullptr;
    cudaGetSymbolAddress((void**)&scr, g_scratch);

    // 1) action embeds -> tanh(action @ W_emb^T + b) into Xv[:, :64] and Xo[:, :64]
    gemm(action, W_emb, scr + O_XV, BATCH, EMB, ANGLE, ANGLE, ANGLE, INDIM,
         scr + O_XO, INDIM, b_emb, 0, 1);

    // 2) attention targets
    gemm(prev_h1_o, Wq_dense, scr + O_TDENSE, BATCH, FEAT, HID, HID, HID, FEAT);
    gemm(prev_h1_v, Wq_feat,  scr + O_TFEAT,  BATCH, FEAT, HID, HID, HID, FEAT);

    // 3) fused object/feature attention -> Xo[:,64:], Xv[:,64:]
    attn_obj_kernel<<<BATCH, 256>>>(denseObj, scr + O_TDENSE, obj_mask,
                                    scr + O_XO + EMB, INDIM);
    attn_obj_kernel<<<BATCH, 256>>>(feature, scr + O_TFEAT, nullptr,
                                    scr + O_XV + EMB, INDIM);

    // 4) LSTM gate GEMMs (input + recurrent, accumulated)
    gemm(scr + O_XV, Wih_v, scr + O_GV, BATCH, GATES, INDIM, INDIM, INDIM, GATES);
    gemm(prev_h1_v,  Whh_v, scr + O_GV, BATCH, GATES, HID, HID, HID, GATES,
         nullptr, 0, nullptr, 1, 0);
    gemm(scr + O_XO, Wih_o, scr + O_GO, BATCH, GATES, INDIM, INDIM, INDIM, GATES);
    gemm(prev_h1_o,  Whh_o, scr + O_GO, BATCH, GATES, HID, HID, HID, GATES,
         nullptr, 0, nullptr, 1, 0);

    // 5) LSTM cells (both use c_0_o, per reference)
    lstm_cell_kernel<<<(BATCH * HID) / 256, 256>>>(
        scr + O_GV, bih_v, bhh_v, c_0_o, out + OFF_H1V, out + OFF_C1V,
        scr + O_HCV + HID, 2 * HID);
    lstm_cell_kernel<<<(BATCH * HID) / 256, 256>>>(
        scr + O_GO, bih_o, bhh_o, c_0_o, out + OFF_H1O, out + OFF_C1O,
        scr + O_HCO + HID, 2 * HID);

    // 6) context attention targets
    gemm(out + OFF_H1V, Wq_av, scr + O_TAVV, BATCH, HID, HID, HID, HID, HID);
    gemm(out + OFF_H1O, Wq_ao, scr + O_TAVO, BATCH, HID, HID, HID, HID, HID);

    // 7) masked context attention -> wctx into htcat[:, :512]
    attn_ctx_kernel<<<BATCH, 256>>>(ctx, scr + O_TAVV, ctx_mask,
                                    scr + O_HCV, 2 * HID);
    attn_ctx_kernel<<<BATCH, 256>>>(ctx, scr + O_TAVO, ctx_mask,
                                    scr + O_HCO, 2 * HID);

    // 8) h_tilde = tanh([wctx, h1] @ Wo^T) -> d_out and cand-concat buffer
    gemm(scr + O_HCV, Wo_av, out + OFF_HTV, BATCH, HID, 2 * HID, 2 * HID,
         2 * HID, HID, scr + O_HC2, 2 * HID, nullptr, 0, 1);
    gemm(scr + O_HCO, Wo_ao, out + OFF_HTO, BATCH, HID, 2 * HID, 2 * HID,
         2 * HID, HID, scr + O_HC2 + HID, 2 * HID, nullptr, 0, 1);

    // 9) candidate target + logits
    gemm(scr + O_HC2, Wq_cand, scr + O_TCAND, BATCH, FEAT, 2 * HID, 2 * HID,
         2 * HID, FEAT);
    cand_logits_kernel<<<(BATCH * NC * 32) / 256, 256>>>(
        cand_feat, scr + O_TCAND, out + OFF_LOGIT);
}